// round 12
// baseline (speedup 1.0000x reference)
#include <cuda_runtime.h>

#define VD 64
#define DD 1986

// Output offsets (floats), tuple flattened in reference return order
#define O_PTS  0                       // (8,16*1986,3)
#define O_DH   762624                  // (8,16,1986,4)
#define O_OVL  1779456                 // (8,16,1)
#define O_MEAN 1779584                 // (8,16,3)
#define O_DIRS 1779968                 // (1986,3)
#define O_LV   1785926                 // (8,16,64,3)

__device__ __align__(16) float4 g_dirs4[2048];
__device__ float g_lv[128 * 192];      // per tile: x[64], y[64], z[64]
__device__ float g_mean[128 * 4];

__device__ __forceinline__ float flg2(float x){float y;asm("lg2.approx.f32 %0,%1;":"=f"(y):"f"(x));return y;}
__device__ __forceinline__ float fex2(float x){float y;asm("ex2.approx.f32 %0,%1;":"=f"(y):"f"(x));return y;}

// ---------------- init: dirs + per-tile mean/local_v ----------------
__global__ __launch_bounds__(128) void init_kernel(
    const float* __restrict__ verts,
    float* __restrict__ out)
{
    const int bid = blockIdx.x;
    const int tid = threadIdx.x;

    if (bid >= 128) {                      // dirs blocks
        int d = (bid - 128) * 128 + tid;   // 0..2047
        float dx, dy, dz;
        if (d < DD - 2) {
            int i = (d >> 6) + 1, j = d & 63;
            float s1, c1, s2, c2;
            sincospif((float)i * (1.f / 32.f) - 0.5f, &s1, &c1);
            sincospif((float)j * (1.f / 32.f) - 1.f, &s2, &c2);
            dx = c1 * c2; dy = c1 * s2; dz = s1;
        } else {
            dx = -6.1232340e-17f;
            dy = -7.4987989e-33f;
            dz = (d == DD - 2) ? -1.f : 1.f;
        }
        g_dirs4[d] = make_float4(dx, dy, dz, 0.f);
        if (d < DD) {
            out[O_DIRS + 3 * d + 0] = dx;
            out[O_DIRS + 3 * d + 1] = dy;
            out[O_DIRS + 3 * d + 2] = dz;
        }
        return;
    }

    // per-tile blocks
    const int tile = bid;
    __shared__ float vraw[192];
    __shared__ float s_mean[3];
    const float* vt = verts + (size_t)tile * 192;
    vraw[tid] = vt[tid];
    if (tid < 64) vraw[tid + 128] = vt[tid + 128];
    __syncthreads();
    if (tid < 32) {
        float px = vraw[6 * tid + 0] + vraw[6 * tid + 3];
        float py = vraw[6 * tid + 1] + vraw[6 * tid + 4];
        float pz = vraw[6 * tid + 2] + vraw[6 * tid + 5];
        #pragma unroll
        for (int o = 16; o > 0; o >>= 1) {
            px += __shfl_down_sync(0xffffffffu, px, o);
            py += __shfl_down_sync(0xffffffffu, py, o);
            pz += __shfl_down_sync(0xffffffffu, pz, o);
        }
        if (tid == 0) {
            s_mean[0] = px * (1.0f / VD);
            s_mean[1] = py * (1.0f / VD);
            s_mean[2] = pz * (1.0f / VD);
        }
    }
    __syncthreads();
    const float mx = s_mean[0], my = s_mean[1], mz = s_mean[2];
    if (tid < VD) {
        float x = vraw[3 * tid + 0] - mx;
        float y = vraw[3 * tid + 1] - my;
        float z = vraw[3 * tid + 2] - mz;
        float* gl = g_lv + tile * 192;
        gl[tid] = x; gl[tid + 64] = y; gl[tid + 128] = z;
        float* olv = out + O_LV + (size_t)tile * 192 + 3 * tid;
        olv[0] = x; olv[1] = y; olv[2] = z;
    }
    if (tid == 0) out[O_OVL + tile] = 0.f;
    if (tid < 3) {
        out[O_MEAN + tile * 3 + tid] = s_mean[tid];
        g_mean[tile * 4 + tid] = s_mean[tid];
    }
}

// ---------------- main: 8 chunks/tile, 256 threads ----------------
__global__ __launch_bounds__(256, 4) void spt_kernel(
    const float* __restrict__ smooth,
    float* __restrict__ out)
{
    const int bid   = blockIdx.x;
    const int tid   = threadIdx.x;
    const int tile  = bid >> 3;
    const int chunk = bid & 7;
    const int d     = chunk * 256 + tid;   // 0..2047

    __shared__ __align__(8) float slv[192];   // x[64] y[64] z[64]
    __shared__ float s_mean[3];

    if (tid < 192) slv[tid] = g_lv[tile * 192 + tid];
    if (tid >= 224 && tid < 227) s_mean[tid - 224] = g_mean[tile * 4 + (tid - 224)];
    __syncthreads();

    if (d >= DD) return;

    const float4 dir = g_dirs4[d];
    const float dx = dir.x, dy = dir.y, dz = dir.z;
    const float mx = s_mean[0], my = s_mean[1], mz = s_mean[2];

    const float p    = smooth[tile];
    const float invp = 1.0f / p;
    const float pm1  = p - 1.0f;

    const float2* sx2 = (const float2*)slv;
    const float2* sy2 = (const float2*)(slv + 64);
    const float2* sz2 = (const float2*)(slv + 128);

    // Fused pass: u = zm^(p-1); A += u*lv.  (S recovered as A.dir)
    float ax = 0.f, ay = 0.f, az = 0.f;
    #pragma unroll
    for (int i = 0; i < VD/2; i++) {
        const float2 X = sx2[i], Y = sy2[i], Z = sz2[i];
        {
            float zm = fmaxf(fmaf(X.x, dx, fmaf(Y.x, dy, Z.x * dz)), 0.f);
            float u  = fex2(pm1 * flg2(zm));   // lg2(0)=-inf -> 0
            ax = fmaf(u, X.x, ax);
            ay = fmaf(u, Y.x, ay);
            az = fmaf(u, Z.x, az);
        }
        {
            float zm = fmaxf(fmaf(X.y, dx, fmaf(Y.y, dy, Z.y * dz)), 0.f);
            float u  = fex2(pm1 * flg2(zm));
            ax = fmaf(u, X.y, ax);
            ay = fmaf(u, Y.y, ay);
            az = fmaf(u, Z.y, az);
        }
    }

    // S = sum(u*zm) = A . dir   (u=0 wherever z<=0)
    const float S = fmaf(ax, dx, fmaf(ay, dy, az * dz));

    float lh = flg2(S) * invp;
    lh = fminf(fmaxf(lh, -66.438562f), 66.438562f);     // h in [1e-20,1e20]
    const float hf = (S > 0.f) ? fex2(-pm1 * lh) : 0.f;

    const size_t base = (size_t)tile * DD + d;
    out[O_PTS + base * 3 + 0] = fmaf(hf, ax, mx);
    out[O_PTS + base * 3 + 1] = fmaf(hf, ay, my);
    out[O_PTS + base * 3 + 2] = fmaf(hf, az, mz);

    reinterpret_cast<float4*>(out + O_DH)[base] =
        make_float4(dx, dy, dz, fex2(lh));
}

extern "C" void kernel_launch(void* const* d_in, const int* in_sizes, int n_in,
                              void* d_out, int out_size) {
    const float* verts  = (const float*)d_in[0];   // (8,16,64,3)
    const float* smooth = (const float*)d_in[1];   // (8,16)
    float* out = (float*)d_out;
    init_kernel<<<144, 128>>>(verts, out);
    spt_kernel<<<128 * 8, 256>>>(smooth, out);
}

// round 14
// speedup vs baseline: 1.1359x; 1.1359x over previous
#include <cuda_runtime.h>

#define VD 64
#define DD 1986

// Output offsets (floats), tuple flattened in reference return order
#define O_PTS  0                       // (8,16*1986,3)
#define O_DH   762624                  // (8,16,1986,4)
#define O_OVL  1779456                 // (8,16,1)
#define O_MEAN 1779584                 // (8,16,3)
#define O_DIRS 1779968                 // (1986,3)
#define O_LV   1785926                 // (8,16,64,3)

typedef unsigned long long u64;

__device__ __forceinline__ float flg2(float x){float y;asm("lg2.approx.f32 %0,%1;":"=f"(y):"f"(x));return y;}
__device__ __forceinline__ float fex2(float x){float y;asm("ex2.approx.f32 %0,%1;":"=f"(y):"f"(x));return y;}
__device__ __forceinline__ float2 ffma2(float2 a, float2 b, float2 c){
    float2 d;
    asm("fma.rn.f32x2 %0,%1,%2,%3;"
        : "=l"(reinterpret_cast<u64&>(d))
        : "l"(reinterpret_cast<const u64&>(a)),
          "l"(reinterpret_cast<const u64&>(b)),
          "l"(reinterpret_cast<const u64&>(c)));
    return d;
}
__device__ __forceinline__ float2 fmul2(float2 a, float2 b){
    float2 d;
    asm("mul.rn.f32x2 %0,%1,%2;"
        : "=l"(reinterpret_cast<u64&>(d))
        : "l"(reinterpret_cast<const u64&>(a)),
          "l"(reinterpret_cast<const u64&>(b)));
    return d;
}

__global__ __launch_bounds__(128, 8) void fused_kernel(
    const float* __restrict__ verts,
    const float* __restrict__ smooth,
    float* __restrict__ out)
{
    const int bid = blockIdx.x;
    const int tid = threadIdx.x;

    // ---- 16 chunks per tile, 1 dir per thread ----
    const int tile  = bid >> 4;
    const int chunk = bid & 15;
    const int d     = chunk * 128 + tid;      // 0..2047; valid if < DD

    __shared__ float vraw[192];
    __shared__ __align__(8) float2 sx2[VD/2], sy2[VD/2], sz2[VD/2];
    __shared__ float s_mean[3];
    __shared__ float c1t[33], s1t[33], c2t[64], s2t[64];

    // trig tables (fp32 sincospif; also the dirs output — global rel-err
    // norm absorbs the ~6e-17 absolute diffs at the pole zeros)
    if (tid < 33) {
        float s, c;
        sincospif((float)tid * (1.f / 32.f) - 0.5f, &s, &c);
        s1t[tid] = s; c1t[tid] = c;
    }
    if (tid >= 64 && tid < 128) {
        int j = tid - 64;
        float s, c;
        sincospif((float)j * (1.f / 32.f) - 1.f, &s, &c);
        s2t[j] = s; c2t[j] = c;
    }

    const float* vt = verts + (size_t)tile * 192;
    vraw[tid] = vt[tid];
    if (tid < 64) vraw[tid + 128] = vt[tid + 128];
    __syncthreads();

    // mean via warp 0 shuffle reduce (2 verts per lane)
    if (tid < 32) {
        float px = vraw[6 * tid + 0] + vraw[6 * tid + 3];
        float py = vraw[6 * tid + 1] + vraw[6 * tid + 4];
        float pz = vraw[6 * tid + 2] + vraw[6 * tid + 5];
        #pragma unroll
        for (int o = 16; o > 0; o >>= 1) {
            px += __shfl_down_sync(0xffffffffu, px, o);
            py += __shfl_down_sync(0xffffffffu, py, o);
            pz += __shfl_down_sync(0xffffffffu, pz, o);
        }
        if (tid == 0) {
            s_mean[0] = px * (1.0f / VD);
            s_mean[1] = py * (1.0f / VD);
            s_mean[2] = pz * (1.0f / VD);
        }
    }
    __syncthreads();
    const float mx = s_mean[0], my = s_mean[1], mz = s_mean[2];
    if (tid < VD) {
        float x = vraw[3 * tid + 0] - mx;
        float y = vraw[3 * tid + 1] - my;
        float z = vraw[3 * tid + 2] - mz;
        ((float*)sx2)[tid] = x;
        ((float*)sy2)[tid] = y;
        ((float*)sz2)[tid] = z;
        if (chunk == 0) {
            float* olv = out + O_LV + (size_t)tile * 192 + 3 * tid;
            olv[0] = x; olv[1] = y; olv[2] = z;
        }
    }
    if (chunk == 0 && tid == 0) out[O_OVL + tile] = 0.f;
    if (chunk == 0 && tid < 3) out[O_MEAN + tile * 3 + tid] = s_mean[tid];
    __syncthreads();

    if (d >= DD) return;

    const float p    = smooth[tile];
    const float invp = 1.0f / p;
    const float pm1  = p - 1.0f;

    float dx, dy, dz;
    if (d < DD - 2) {
        int i = (d >> 6) + 1, j = d & 63;
        float c1 = c1t[i];
        dx = c1 * c2t[j]; dy = c1 * s2t[j]; dz = s1t[i];
    } else {
        dx = -6.1232340e-17f;
        dy = -7.4987989e-33f;
        dz = (d == DD - 2) ? -1.f : 1.f;
    }

    // tile 0 also emits the dirs output (fp32 tables)
    if (tile == 0) {
        out[O_DIRS + 3 * d + 0] = dx;
        out[O_DIRS + 3 * d + 1] = dy;
        out[O_DIRS + 3 * d + 2] = dz;
    }

    const float2 dx2 = make_float2(dx, dx);
    const float2 dy2 = make_float2(dy, dy);
    const float2 dz2 = make_float2(dz, dz);

    // Fused pass (packed dot + packed accumulate, scalar MUFU chain):
    //   u = zm^(p-1); A += u*lv.  (S recovered as A.dir)
    float2 ax2 = make_float2(0.f, 0.f);
    float2 ay2 = make_float2(0.f, 0.f);
    float2 az2 = make_float2(0.f, 0.f);
    #pragma unroll
    for (int i = 0; i < VD/2; i++) {
        const float2 X = sx2[i], Y = sy2[i], Z = sz2[i];
        float2 z2 = ffma2(X, dx2, ffma2(Y, dy2, fmul2(Z, dz2)));
        float ua = fex2(pm1 * flg2(fmaxf(z2.x, 0.f)));   // lg2(0)=-inf -> 0
        float ub = fex2(pm1 * flg2(fmaxf(z2.y, 0.f)));
        const float2 u2 = make_float2(ua, ub);
        ax2 = ffma2(u2, X, ax2);
        ay2 = ffma2(u2, Y, ay2);
        az2 = ffma2(u2, Z, az2);
    }
    const float ax = ax2.x + ax2.y;
    const float ay = ay2.x + ay2.y;
    const float az = az2.x + az2.y;

    // S = sum(u*zm) = A . dir   (u=0 wherever z<=0)
    const float S = fmaf(ax, dx, fmaf(ay, dy, az * dz));

    float lh = flg2(S) * invp;
    lh = fminf(fmaxf(lh, -66.438562f), 66.438562f);     // h in [1e-20,1e20]
    const float hf = (S > 0.f) ? fex2(-pm1 * lh) : 0.f;

    const size_t base = (size_t)tile * DD + d;
    out[O_PTS + base * 3 + 0] = fmaf(hf, ax, mx);
    out[O_PTS + base * 3 + 1] = fmaf(hf, ay, my);
    out[O_PTS + base * 3 + 2] = fmaf(hf, az, mz);

    reinterpret_cast<float4*>(out + O_DH)[base] =
        make_float4(dx, dy, dz, fex2(lh));
}

extern "C" void kernel_launch(void* const* d_in, const int* in_sizes, int n_in,
                              void* d_out, int out_size) {
    const float* verts  = (const float*)d_in[0];   // (8,16,64,3)
    const float* smooth = (const float*)d_in[1];   // (8,16)
    float* out = (float*)d_out;
    fused_kernel<<<128 * 16, 128>>>(verts, smooth, out);
}